// round 3
// baseline (speedup 1.0000x reference)
#include <cuda_runtime.h>
#include <cuda_bf16.h>
#include <cstdint>

// Problem constants
#define BB 4
#define TT 2048
#define CC 2048
#define HH 16
#define DD 128
#define QKSCALE 0.08838834764831845f  // 1/sqrt(128)

// ---------------------------------------------------------------------------
// Device-global scratch (allocation-free rule)
// ---------------------------------------------------------------------------
__device__ float g_q[(size_t)BB * HH * TT * DD];
__device__ float g_k[(size_t)BB * HH * TT * DD];
__device__ float g_v[(size_t)BB * HH * TT * DD];
__device__ __nv_bfloat16 g_xh[(size_t)BB * TT * CC];
__device__ __nv_bfloat16 g_xl[(size_t)BB * TT * CC];
__device__ __nv_bfloat16 g_wqh[(size_t)3 * CC * CC];  // Wqkv^T [N=3C][K=C]
__device__ __nv_bfloat16 g_wql[(size_t)3 * CC * CC];
__device__ __nv_bfloat16 g_wph[(size_t)CC * CC];      // Wproj^T [N=C][K=C]
__device__ __nv_bfloat16 g_wpl[(size_t)CC * CC];
__device__ __nv_bfloat16 g_aoh[(size_t)BB * TT * CC]; // attn out hi/lo [B,T,C]
__device__ __nv_bfloat16 g_aol[(size_t)BB * TT * CC];

// ---------------------------------------------------------------------------
// Base-PTX helpers (sm_80-class: work on compute_103 base target)
// ---------------------------------------------------------------------------
__device__ __forceinline__ uint32_t smem_u32(const void* p) {
    uint32_t a;
    asm("{ .reg .u64 t; cvta.to.shared.u64 t, %1; cvt.u32.u64 %0, t; }"
        : "=r"(a) : "l"(p));
    return a;
}
__device__ __forceinline__ void cp16(uint32_t s, const void* g) {
    asm volatile("cp.async.cg.shared.global [%0], [%1], 16;" :: "r"(s), "l"(g));
}
#define CP_COMMIT() asm volatile("cp.async.commit_group;")
#define CP_WAIT(n)  asm volatile("cp.async.wait_group %0;" :: "n"(n))

__device__ __forceinline__ void ldsm4(uint32_t& r0, uint32_t& r1,
                                      uint32_t& r2, uint32_t& r3, uint32_t a) {
    asm volatile("ldmatrix.sync.aligned.m8n8.x4.shared.b16 {%0,%1,%2,%3}, [%4];"
                 : "=r"(r0), "=r"(r1), "=r"(r2), "=r"(r3) : "r"(a));
}
__device__ __forceinline__ void mma16816(float* c, const uint32_t* a,
                                         uint32_t b0, uint32_t b1) {
    asm volatile(
        "mma.sync.aligned.m16n8k16.row.col.f32.bf16.bf16.f32 "
        "{%0,%1,%2,%3}, {%4,%5,%6,%7}, {%8,%9}, {%0,%1,%2,%3};"
        : "+f"(c[0]), "+f"(c[1]), "+f"(c[2]), "+f"(c[3])
        : "r"(a[0]), "r"(a[1]), "r"(a[2]), "r"(a[3]), "r"(b0), "r"(b1));
}

// ---------------------------------------------------------------------------
// Precision split helpers
// ---------------------------------------------------------------------------
__device__ __forceinline__ void split_hl(float v, __nv_bfloat16& h, __nv_bfloat16& l) {
    h = __float2bfloat16(v);
    l = __float2bfloat16(v - __bfloat162float(h));
}

__global__ __launch_bounds__(256) void convert_x_kernel(
    const float* __restrict__ x, __nv_bfloat16* __restrict__ hh,
    __nv_bfloat16* __restrict__ ll, int n4)
{
    int stride = gridDim.x * blockDim.x;
    for (int i = blockIdx.x * blockDim.x + threadIdx.x; i < n4; i += stride) {
        float4 f = ((const float4*)x)[i];
        __nv_bfloat16 h0, l0, h1, l1, h2, l2, h3, l3;
        split_hl(f.x, h0, l0); split_hl(f.y, h1, l1);
        split_hl(f.z, h2, l2); split_hl(f.w, h3, l3);
        ((__nv_bfloat162*)hh)[2 * i]     = __nv_bfloat162{h0, h1};
        ((__nv_bfloat162*)hh)[2 * i + 1] = __nv_bfloat162{h2, h3};
        ((__nv_bfloat162*)ll)[2 * i]     = __nv_bfloat162{l0, l1};
        ((__nv_bfloat162*)ll)[2 * i + 1] = __nv_bfloat162{l2, l3};
    }
}

// W [K,N] fp32 -> W^T [N,K] bf16 hi/lo (tiled transpose)
__global__ __launch_bounds__(256) void convert_wT_kernel(
    const float* __restrict__ W, __nv_bfloat16* __restrict__ hT,
    __nv_bfloat16* __restrict__ lT, int K, int N)
{
    __shared__ float t[32][33];
    int n0 = blockIdx.x * 32, k0 = blockIdx.y * 32;
    int tx = threadIdx.x & 31, ty = threadIdx.x >> 5;  // 32 x 8
#pragma unroll
    for (int r = 0; r < 32; r += 8)
        t[ty + r][tx] = W[(size_t)(k0 + ty + r) * N + n0 + tx];
    __syncthreads();
#pragma unroll
    for (int r = 0; r < 32; r += 8) {
        float v = t[tx][ty + r];
        __nv_bfloat16 h, l;
        split_hl(v, h, l);
        size_t o = (size_t)(n0 + ty + r) * K + k0 + tx;
        hT[o] = h;
        lT[o] = l;
    }
}

// ---------------------------------------------------------------------------
// HMMA GEMM: C[M,N] = A[M,K] @ B^T (+bias), A/B given as bf16 hi/lo pairs.
// D = Ah*Bh + Ah*Bl + Al*Bh (fp32 accum). CTA 128x128, BK=32, 8 warps (64x32).
// Smem: double buffer x 4 operands x [128 rows][32 bf16] swizzled.
// MODE 0: scatter q/k/v.  MODE 1: row-major Cout.
// ---------------------------------------------------------------------------
#define GEMM_SMEM 65536

template <int MODE>
__global__ __launch_bounds__(256) void hmma_gemm(
    const __nv_bfloat16* __restrict__ Ah, const __nv_bfloat16* __restrict__ Al,
    const __nv_bfloat16* __restrict__ BhT, const __nv_bfloat16* __restrict__ BlT,
    const float* __restrict__ bias, float* __restrict__ Cout, int Ntot, int K)
{
    extern __shared__ char smem[];
    const uint32_t sbase = smem_u32(smem);

    const int tid = threadIdx.x;
    const int lane = tid & 31;
    const int wid = tid >> 5;
    const int warp_m = wid >> 2;    // 0..1  (64 rows each)
    const int warp_n = wid & 3;     // 0..3  (32 cols each)
    const int m0 = blockIdx.y * 128;
    const int n0 = blockIdx.x * 128;

    // --- cp.async slots: thread copies rows (crow, crow+64), chunk cchunk ---
    const int crow = tid >> 2;              // 0..63
    const int cchunk = tid & 3;             // 16B chunk in 64B row
    const uint32_t soff0 = crow * 64 + ((cchunk ^ ((crow >> 1) & 3)) << 4);
    const uint32_t soff1 = soff0 + 64 * 64; // row+64 has same swizzle phase
    const size_t rstep = (size_t)64 * K;
    const __nv_bfloat16* gAh = Ah  + (size_t)(m0 + crow) * K + cchunk * 8;
    const __nv_bfloat16* gAl = Al  + (size_t)(m0 + crow) * K + cchunk * 8;
    const __nv_bfloat16* gBh = BhT + (size_t)(n0 + crow) * K + cchunk * 8;
    const __nv_bfloat16* gBl = BlT + (size_t)(n0 + crow) * K + cchunk * 8;

#define ISSUE(kc, buf) do {                                                  \
    size_t ko = (size_t)(kc) * 32;                                           \
    uint32_t sb = sbase + (buf) * 32768;                                     \
    cp16(sb + soff0,         gAh + ko);                                      \
    cp16(sb + soff1,         gAh + rstep + ko);                              \
    cp16(sb + 8192 + soff0,  gAl + ko);                                      \
    cp16(sb + 8192 + soff1,  gAl + rstep + ko);                              \
    cp16(sb + 16384 + soff0, gBh + ko);                                      \
    cp16(sb + 16384 + soff1, gBh + rstep + ko);                              \
    cp16(sb + 24576 + soff0, gBl + ko);                                      \
    cp16(sb + 24576 + soff1, gBl + rstep + ko);                              \
} while (0)

    // --- ldmatrix lane addressing ---
    const int akg = lane >> 4;                       // k-half for A
    const uint32_t aswz = ((lane & 15) >> 1) & 3;
    uint32_t arow[4];
#pragma unroll
    for (int mt = 0; mt < 4; mt++)
        arow[mt] = (uint32_t)(warp_m * 64 + mt * 16 + (lane & 15)) * 64;

    const int bkg = (lane >> 3) & 1;                 // k-half for B
    const int brbase = warp_n * 32 + (lane & 7) + ((lane >> 4) & 1) * 8;
    const uint32_t bswz = ((uint32_t)brbase >> 1) & 3;
    uint32_t brow[2] = {(uint32_t)brbase * 64, (uint32_t)(brbase + 16) * 64};

    float acc[4][4][4];
#pragma unroll
    for (int mt = 0; mt < 4; mt++)
#pragma unroll
        for (int j = 0; j < 4; j++)
#pragma unroll
            for (int e = 0; e < 4; e++) acc[mt][j][e] = 0.f;

    const int nch = K / 32;
    ISSUE(0, 0);
    CP_COMMIT();

    for (int kc = 0; kc < nch; kc++) {
        const int cur = kc & 1;
        if (kc + 1 < nch) {
            ISSUE(kc + 1, cur ^ 1);
            CP_COMMIT();
            CP_WAIT(1);
        } else {
            CP_WAIT(0);
        }
        __syncthreads();

        const uint32_t bb = sbase + cur * 32768;
#pragma unroll
        for (int s = 0; s < 2; s++) {
            uint32_t fAh[4][4], fAl[4][4], fBh[2][4], fBl[2][4];
            const uint32_t aco = (uint32_t)((2 * s + akg) ^ aswz) << 4;
            const uint32_t bco = (uint32_t)((2 * s + bkg) ^ bswz) << 4;
#pragma unroll
            for (int mt = 0; mt < 4; mt++) {
                uint32_t ad = bb + arow[mt] + aco;
                ldsm4(fAh[mt][0], fAh[mt][1], fAh[mt][2], fAh[mt][3], ad);
                ldsm4(fAl[mt][0], fAl[mt][1], fAl[mt][2], fAl[mt][3], ad + 8192);
            }
#pragma unroll
            for (int nt = 0; nt < 2; nt++) {
                uint32_t bd = bb + 16384 + brow[nt] + bco;
                ldsm4(fBh[nt][0], fBh[nt][1], fBh[nt][2], fBh[nt][3], bd);
                ldsm4(fBl[nt][0], fBl[nt][1], fBl[nt][2], fBl[nt][3], bd + 8192);
            }
#pragma unroll
            for (int mt = 0; mt < 4; mt++)
#pragma unroll
                for (int j = 0; j < 4; j++) {
                    const int nt = j >> 1, hf = (j & 1) * 2;
                    mma16816(acc[mt][j], fAh[mt], fBh[nt][hf], fBh[nt][hf + 1]);
                    mma16816(acc[mt][j], fAh[mt], fBl[nt][hf], fBl[nt][hf + 1]);
                    mma16816(acc[mt][j], fAl[mt], fBh[nt][hf], fBh[nt][hf + 1]);
                }
        }
        __syncthreads();
    }
#undef ISSUE

    // --- Epilogue ---
    const int g = lane >> 2, cq = (lane & 3) * 2;
#pragma unroll
    for (int mt = 0; mt < 4; mt++)
#pragma unroll
        for (int j = 0; j < 4; j++)
#pragma unroll
            for (int e = 0; e < 4; e++) {
                int m = m0 + warp_m * 64 + mt * 16 + g + (e >> 1) * 8;
                int n = n0 + warp_n * 32 + j * 8 + cq + (e & 1);
                float v = acc[mt][j][e] + bias[n];
                if (MODE == 0) {
                    int which = n >> 11;
                    int h = (n >> 7) & 15;
                    int d = n & 127;
                    int b = m >> 11;
                    int t = m & 2047;
                    size_t idx = (((size_t)b * HH + h) * TT + t) * DD + d;
                    if (which == 0)      g_q[idx] = v * QKSCALE;
                    else if (which == 1) g_k[idx] = v;
                    else                 g_v[idx] = v;
                } else {
                    Cout[(size_t)m * Ntot + n] = v;
                }
            }
}

// ---------------------------------------------------------------------------
// Flash attention (causal), fp32 SIMT (unchanged from R1; emits bf16 hi/lo)
// ---------------------------------------------------------------------------
#define QPAD 132
#define PPAD 68
#define ATTN_SMEM ((3 * 64 * QPAD + 64 * PPAD) * (int)sizeof(float))

__global__ __launch_bounds__(256) void attn_kernel()
{
    extern __shared__ float sm[];
    float* Qs = sm;
    float* Ks = sm + 64 * QPAD;
    float* Vs = sm + 2 * 64 * QPAD;
    float* Ps = sm + 3 * 64 * QPAD;

    const int tid = threadIdx.x;
    const int tx = tid & 15;
    const int ty = tid >> 4;
    const int qt = blockIdx.x;
    const int h = blockIdx.y;
    const int b = blockIdx.z;

    const size_t base = (((size_t)b * HH + h) * TT) * DD;

#pragma unroll
    for (int i = 0; i < 8; i++) {
        int pp = tid + i * 256;
        int row = pp >> 5;
        int d = (pp & 31) * 4;
        *(float4*)&Qs[row * QPAD + d] =
            *(const float4*)&g_q[base + (size_t)(qt * 64 + row) * DD + d];
    }

    float o[4][8];
#pragma unroll
    for (int i = 0; i < 4; i++)
#pragma unroll
        for (int d = 0; d < 8; d++) o[i][d] = 0.f;
    float mrow[4] = {-1e30f, -1e30f, -1e30f, -1e30f};
    float lrow[4] = {0.f, 0.f, 0.f, 0.f};

    for (int jt = 0; jt <= qt; jt++) {
        __syncthreads();
#pragma unroll
        for (int i = 0; i < 8; i++) {
            int pp = tid + i * 256;
            int row = pp >> 5;
            int d = (pp & 31) * 4;
            size_t gidx = base + (size_t)(jt * 64 + row) * DD + d;
            *(float4*)&Ks[row * QPAD + d] = *(const float4*)&g_k[gidx];
            *(float4*)&Vs[row * QPAD + d] = *(const float4*)&g_v[gidx];
        }
        __syncthreads();

        float s[4][4];
#pragma unroll
        for (int i = 0; i < 4; i++)
#pragma unroll
            for (int j = 0; j < 4; j++) s[i][j] = 0.f;

#pragma unroll 8
        for (int d0 = 0; d0 < DD; d0 += 4) {
            float4 a[4], kk[4];
#pragma unroll
            for (int i = 0; i < 4; i++)
                a[i] = *(float4*)&Qs[(ty * 4 + i) * QPAD + d0];
#pragma unroll
            for (int j = 0; j < 4; j++)
                kk[j] = *(float4*)&Ks[(tx * 4 + j) * QPAD + d0];
#pragma unroll
            for (int i = 0; i < 4; i++)
#pragma unroll
                for (int j = 0; j < 4; j++)
                    s[i][j] += a[i].x * kk[j].x + a[i].y * kk[j].y +
                               a[i].z * kk[j].z + a[i].w * kk[j].w;
        }

        if (jt == qt) {
#pragma unroll
            for (int i = 0; i < 4; i++)
#pragma unroll
                for (int j = 0; j < 4; j++)
                    if (tx * 4 + j > ty * 4 + i) s[i][j] = -1e30f;
        }

#pragma unroll
        for (int i = 0; i < 4; i++) {
            float mx = fmaxf(fmaxf(s[i][0], s[i][1]), fmaxf(s[i][2], s[i][3]));
#pragma unroll
            for (int off = 8; off >= 1; off >>= 1)
                mx = fmaxf(mx, __shfl_xor_sync(0xffffffffu, mx, off, 16));
            float nm = fmaxf(mrow[i], mx);
            float alpha = __expf(mrow[i] - nm);
            mrow[i] = nm;
            float sum = 0.f;
#pragma unroll
            for (int j = 0; j < 4; j++) {
                float p = __expf(s[i][j] - nm);
                Ps[(ty * 4 + i) * PPAD + tx * 4 + j] = p;
                sum += p;
            }
#pragma unroll
            for (int off = 8; off >= 1; off >>= 1)
                sum += __shfl_xor_sync(0xffffffffu, sum, off, 16);
            lrow[i] = lrow[i] * alpha + sum;
#pragma unroll
            for (int d = 0; d < 8; d++) o[i][d] *= alpha;
        }
        __syncthreads();

#pragma unroll 8
        for (int col = 0; col < 64; col++) {
            float4 v0 = *(float4*)&Vs[col * QPAD + tx * 8];
            float4 v1 = *(float4*)&Vs[col * QPAD + tx * 8 + 4];
#pragma unroll
            for (int i = 0; i < 4; i++) {
                float p = Ps[(ty * 4 + i) * PPAD + col];
                o[i][0] += p * v0.x; o[i][1] += p * v0.y;
                o[i][2] += p * v0.z; o[i][3] += p * v0.w;
                o[i][4] += p * v1.x; o[i][5] += p * v1.y;
                o[i][6] += p * v1.z; o[i][7] += p * v1.w;
            }
        }
    }

#pragma unroll
    for (int i = 0; i < 4; i++) {
        float inv = 1.f / lrow[i];
        int q = qt * 64 + ty * 4 + i;
        size_t ob = ((size_t)b * TT + q) * CC + (size_t)h * DD + tx * 8;
#pragma unroll
        for (int d = 0; d < 8; d++) {
            float val = o[i][d] * inv;
            __nv_bfloat16 hh, ll;
            split_hl(val, hh, ll);
            g_aoh[ob + d] = hh;
            g_aol[ob + d] = ll;
        }
    }
}

// ---------------------------------------------------------------------------
extern "C" void kernel_launch(void* const* d_in, const int* in_sizes, int n_in,
                              void* d_out, int out_size)
{
    (void)in_sizes; (void)n_in; (void)out_size;
    const float* x     = (const float*)d_in[0];
    const float* Wqkv  = (const float*)d_in[1];
    const float* bqkv  = (const float*)d_in[2];
    const float* Wproj = (const float*)d_in[3];
    const float* bproj = (const float*)d_in[4];
    float* out = (float*)d_out;

    cudaFuncSetAttribute(attn_kernel,
                         cudaFuncAttributeMaxDynamicSharedMemorySize, ATTN_SMEM);
    cudaFuncSetAttribute(hmma_gemm<0>,
                         cudaFuncAttributeMaxDynamicSharedMemorySize, GEMM_SMEM);
    cudaFuncSetAttribute(hmma_gemm<1>,
                         cudaFuncAttributeMaxDynamicSharedMemorySize, GEMM_SMEM);

    __nv_bfloat16 *xh, *xl, *wqh, *wql, *wph, *wpl, *aoh, *aol;
    cudaGetSymbolAddress((void**)&xh, g_xh);
    cudaGetSymbolAddress((void**)&xl, g_xl);
    cudaGetSymbolAddress((void**)&wqh, g_wqh);
    cudaGetSymbolAddress((void**)&wql, g_wql);
    cudaGetSymbolAddress((void**)&wph, g_wph);
    cudaGetSymbolAddress((void**)&wpl, g_wpl);
    cudaGetSymbolAddress((void**)&aoh, g_aoh);
    cudaGetSymbolAddress((void**)&aol, g_aol);

    // 1) Split to bf16 hi/lo (weights transposed to [N,K])
    convert_x_kernel<<<4096, 256>>>(x, xh, xl, (BB * TT * CC) / 4);
    convert_wT_kernel<<<dim3(3 * CC / 32, CC / 32), 256>>>(Wqkv, wqh, wql, CC, 3 * CC);
    convert_wT_kernel<<<dim3(CC / 32, CC / 32), 256>>>(Wproj, wph, wpl, CC, CC);

    // 2) QKV projection on HMMA tensor cores, scatter to [B,H,T,D]
    hmma_gemm<0><<<dim3(48, 64), 256, GEMM_SMEM>>>(
        xh, xl, wqh, wql, bqkv, nullptr, 3 * CC, CC);

    // 3) Causal flash attention (fp32 SIMT)
    attn_kernel<<<dim3(TT / 64, HH, BB), 256, ATTN_SMEM>>>();

    // 4) Output projection on HMMA tensor cores
    hmma_gemm<1><<<dim3(16, 64), 256, GEMM_SMEM>>>(
        aoh, aol, wph, wpl, bproj, out, CC, CC);
}

// round 15
// speedup vs baseline: 4.0333x; 4.0333x over previous
#include <cuda_runtime.h>
#include <cuda_bf16.h>
#include <cstdint>

// Problem constants
#define BB 4
#define TT 2048
#define CC 2048
#define HH 16
#define DD 128
#define QKSCALE 0.08838834764831845f  // 1/sqrt(128)

// ---------------------------------------------------------------------------
// Device-global scratch (allocation-free rule)
// ---------------------------------------------------------------------------
__device__ __nv_bfloat16 g_qh[(size_t)BB * HH * TT * DD];
__device__ __nv_bfloat16 g_ql[(size_t)BB * HH * TT * DD];
__device__ __nv_bfloat16 g_kh[(size_t)BB * HH * TT * DD];
__device__ __nv_bfloat16 g_kl[(size_t)BB * HH * TT * DD];
__device__ __nv_bfloat16 g_vh[(size_t)BB * HH * TT * DD];
__device__ __nv_bfloat16 g_vl[(size_t)BB * HH * TT * DD];
__device__ __nv_bfloat16 g_xh[(size_t)BB * TT * CC];
__device__ __nv_bfloat16 g_xl[(size_t)BB * TT * CC];
__device__ __nv_bfloat16 g_wqh[(size_t)3 * CC * CC];  // Wqkv^T [N=3C][K=C]
__device__ __nv_bfloat16 g_wql[(size_t)3 * CC * CC];
__device__ __nv_bfloat16 g_wph[(size_t)CC * CC];      // Wproj^T [N=C][K=C]
__device__ __nv_bfloat16 g_wpl[(size_t)CC * CC];
__device__ __nv_bfloat16 g_aoh[(size_t)BB * TT * CC]; // attn out hi/lo [B,T,C]
__device__ __nv_bfloat16 g_aol[(size_t)BB * TT * CC];

// ---------------------------------------------------------------------------
// Base-PTX helpers
// ---------------------------------------------------------------------------
__device__ __forceinline__ uint32_t smem_u32(const void* p) {
    uint32_t a;
    asm("{ .reg .u64 t; cvta.to.shared.u64 t, %1; cvt.u32.u64 %0, t; }"
        : "=r"(a) : "l"(p));
    return a;
}
__device__ __forceinline__ void cp16(uint32_t s, const void* g) {
    asm volatile("cp.async.cg.shared.global [%0], [%1], 16;" :: "r"(s), "l"(g));
}
#define CP_COMMIT() asm volatile("cp.async.commit_group;")
#define CP_WAIT(n)  asm volatile("cp.async.wait_group %0;" :: "n"(n))

__device__ __forceinline__ void ldsm4(uint32_t& r0, uint32_t& r1,
                                      uint32_t& r2, uint32_t& r3, uint32_t a) {
    asm volatile("ldmatrix.sync.aligned.m8n8.x4.shared.b16 {%0,%1,%2,%3}, [%4];"
                 : "=r"(r0), "=r"(r1), "=r"(r2), "=r"(r3) : "r"(a));
}
__device__ __forceinline__ void ldsm4t(uint32_t& r0, uint32_t& r1,
                                       uint32_t& r2, uint32_t& r3, uint32_t a) {
    asm volatile("ldmatrix.sync.aligned.m8n8.x4.trans.shared.b16 {%0,%1,%2,%3}, [%4];"
                 : "=r"(r0), "=r"(r1), "=r"(r2), "=r"(r3) : "r"(a));
}
__device__ __forceinline__ void mma16816(float* c, const uint32_t* a,
                                         uint32_t b0, uint32_t b1) {
    asm volatile(
        "mma.sync.aligned.m16n8k16.row.col.f32.bf16.bf16.f32 "
        "{%0,%1,%2,%3}, {%4,%5,%6,%7}, {%8,%9}, {%0,%1,%2,%3};"
        : "+f"(c[0]), "+f"(c[1]), "+f"(c[2]), "+f"(c[3])
        : "r"(a[0]), "r"(a[1]), "r"(a[2]), "r"(a[3]), "r"(b0), "r"(b1));
}

__device__ __forceinline__ void split_hl(float v, __nv_bfloat16& h, __nv_bfloat16& l) {
    h = __float2bfloat16(v);
    l = __float2bfloat16(v - __bfloat162float(h));
}
// split pair (p0,p1) -> packed bf16x2 hi-word + lo-word (p0 in low half)
__device__ __forceinline__ void split2(float p0, float p1, uint32_t& hw, uint32_t& lw) {
    __nv_bfloat16 h0 = __float2bfloat16(p0), h1 = __float2bfloat16(p1);
    float l0 = p0 - __bfloat162float(h0), l1 = p1 - __bfloat162float(h1);
    __nv_bfloat162 hh{h0, h1};
    __nv_bfloat162 ll{__float2bfloat16(l0), __float2bfloat16(l1)};
    hw = *(uint32_t*)&hh;
    lw = *(uint32_t*)&ll;
}

// ---------------------------------------------------------------------------
// Converters
// ---------------------------------------------------------------------------
__global__ __launch_bounds__(256) void convert_x_kernel(
    const float* __restrict__ x, __nv_bfloat16* __restrict__ hh,
    __nv_bfloat16* __restrict__ ll, int n4)
{
    int stride = gridDim.x * blockDim.x;
    for (int i = blockIdx.x * blockDim.x + threadIdx.x; i < n4; i += stride) {
        float4 f = ((const float4*)x)[i];
        __nv_bfloat16 h0, l0, h1, l1, h2, l2, h3, l3;
        split_hl(f.x, h0, l0); split_hl(f.y, h1, l1);
        split_hl(f.z, h2, l2); split_hl(f.w, h3, l3);
        ((__nv_bfloat162*)hh)[2 * i]     = __nv_bfloat162{h0, h1};
        ((__nv_bfloat162*)hh)[2 * i + 1] = __nv_bfloat162{h2, h3};
        ((__nv_bfloat162*)ll)[2 * i]     = __nv_bfloat162{l0, l1};
        ((__nv_bfloat162*)ll)[2 * i + 1] = __nv_bfloat162{l2, l3};
    }
}

__global__ __launch_bounds__(256) void convert_wT_kernel(
    const float* __restrict__ W, __nv_bfloat16* __restrict__ hT,
    __nv_bfloat16* __restrict__ lT, int K, int N)
{
    __shared__ float t[32][33];
    int n0 = blockIdx.x * 32, k0 = blockIdx.y * 32;
    int tx = threadIdx.x & 31, ty = threadIdx.x >> 5;
#pragma unroll
    for (int r = 0; r < 32; r += 8)
        t[ty + r][tx] = W[(size_t)(k0 + ty + r) * N + n0 + tx];
    __syncthreads();
#pragma unroll
    for (int r = 0; r < 32; r += 8) {
        float v = t[tx][ty + r];
        __nv_bfloat16 h, l;
        split_hl(v, h, l);
        size_t o = (size_t)(n0 + ty + r) * K + k0 + tx;
        hT[o] = h;
        lT[o] = l;
    }
}

// ---------------------------------------------------------------------------
// HMMA GEMM: C = A @ B^T (+bias); bf16 hi/lo 3-pass. CTA 128x128, BK=32,
// 8 warps (64x32 each), double-buffered cp.async, 2 CTAs/SM.
// MODE 0: emit q/k/v bf16 hi/lo (q scaled).  MODE 1: fp32 row-major Cout.
// ---------------------------------------------------------------------------
#define GEMM_SMEM 65536

template <int MODE>
__global__ __launch_bounds__(256, 2) void hmma_gemm(
    const __nv_bfloat16* __restrict__ Ah, const __nv_bfloat16* __restrict__ Al,
    const __nv_bfloat16* __restrict__ BhT, const __nv_bfloat16* __restrict__ BlT,
    const float* __restrict__ bias, float* __restrict__ Cout, int Ntot, int K)
{
    extern __shared__ char smem[];
    const uint32_t sbase = smem_u32(smem);

    const int tid = threadIdx.x;
    const int lane = tid & 31;
    const int wid = tid >> 5;
    const int warp_m = wid >> 2;
    const int warp_n = wid & 3;
    const int m0 = blockIdx.y * 128;
    const int n0 = blockIdx.x * 128;

    const int crow = tid >> 2;
    const int cchunk = tid & 3;
    const uint32_t soff0 = crow * 64 + ((cchunk ^ ((crow >> 1) & 3)) << 4);
    const uint32_t soff1 = soff0 + 64 * 64;
    const size_t rstep = (size_t)64 * K;
    const __nv_bfloat16* gAh = Ah  + (size_t)(m0 + crow) * K + cchunk * 8;
    const __nv_bfloat16* gAl = Al  + (size_t)(m0 + crow) * K + cchunk * 8;
    const __nv_bfloat16* gBh = BhT + (size_t)(n0 + crow) * K + cchunk * 8;
    const __nv_bfloat16* gBl = BlT + (size_t)(n0 + crow) * K + cchunk * 8;

#define ISSUE(kc, buf) do {                                                  \
    size_t ko = (size_t)(kc) * 32;                                           \
    uint32_t sb = sbase + (buf) * 32768;                                     \
    cp16(sb + soff0,         gAh + ko);                                      \
    cp16(sb + soff1,         gAh + rstep + ko);                              \
    cp16(sb + 8192 + soff0,  gAl + ko);                                      \
    cp16(sb + 8192 + soff1,  gAl + rstep + ko);                              \
    cp16(sb + 16384 + soff0, gBh + ko);                                      \
    cp16(sb + 16384 + soff1, gBh + rstep + ko);                              \
    cp16(sb + 24576 + soff0, gBl + ko);                                      \
    cp16(sb + 24576 + soff1, gBl + rstep + ko);                              \
} while (0)

    const int akg = lane >> 4;
    const uint32_t aswz = ((lane & 15) >> 1) & 3;
    uint32_t arow[4];
#pragma unroll
    for (int mt = 0; mt < 4; mt++)
        arow[mt] = (uint32_t)(warp_m * 64 + mt * 16 + (lane & 15)) * 64;

    const int bkg = (lane >> 3) & 1;
    const int brbase = warp_n * 32 + (lane & 7) + ((lane >> 4) & 1) * 8;
    const uint32_t bswz = ((uint32_t)brbase >> 1) & 3;
    uint32_t brow[2] = {(uint32_t)brbase * 64, (uint32_t)(brbase + 16) * 64};

    float acc[4][4][4];
#pragma unroll
    for (int mt = 0; mt < 4; mt++)
#pragma unroll
        for (int j = 0; j < 4; j++)
#pragma unroll
            for (int e = 0; e < 4; e++) acc[mt][j][e] = 0.f;

    const int nch = K / 32;
    ISSUE(0, 0);
    CP_COMMIT();

    for (int kc = 0; kc < nch; kc++) {
        const int cur = kc & 1;
        if (kc + 1 < nch) {
            ISSUE(kc + 1, cur ^ 1);
            CP_COMMIT();
            CP_WAIT(1);
        } else {
            CP_WAIT(0);
        }
        __syncthreads();

        const uint32_t bb = sbase + cur * 32768;
#pragma unroll
        for (int s = 0; s < 2; s++) {
            const uint32_t aco = (uint32_t)((2 * s + akg) ^ aswz) << 4;
            const uint32_t bco = (uint32_t)((2 * s + bkg) ^ bswz) << 4;
            uint32_t fBh[2][4], fBl[2][4];
#pragma unroll
            for (int nt = 0; nt < 2; nt++) {
                uint32_t bd = bb + 16384 + brow[nt] + bco;
                ldsm4(fBh[nt][0], fBh[nt][1], fBh[nt][2], fBh[nt][3], bd);
                ldsm4(fBl[nt][0], fBl[nt][1], fBl[nt][2], fBl[nt][3], bd + 8192);
            }
#pragma unroll
            for (int mt = 0; mt < 4; mt++) {
                uint32_t fAh[4], fAl[4];
                uint32_t ad = bb + arow[mt] + aco;
                ldsm4(fAh[0], fAh[1], fAh[2], fAh[3], ad);
                ldsm4(fAl[0], fAl[1], fAl[2], fAl[3], ad + 8192);
#pragma unroll
                for (int j = 0; j < 4; j++) {
                    const int nt = j >> 1, hf = (j & 1) * 2;
                    mma16816(acc[mt][j], fAh, fBh[nt][hf], fBh[nt][hf + 1]);
                    mma16816(acc[mt][j], fAh, fBl[nt][hf], fBl[nt][hf + 1]);
                    mma16816(acc[mt][j], fAl, fBh[nt][hf], fBh[nt][hf + 1]);
                }
            }
        }
        __syncthreads();
    }
#undef ISSUE

    // --- Epilogue (writes pairs n, n+1) ---
    const int g = lane >> 2, cq = (lane & 3) * 2;
#pragma unroll
    for (int mt = 0; mt < 4; mt++)
#pragma unroll
        for (int j = 0; j < 4; j++)
#pragma unroll
            for (int eh = 0; eh < 2; eh++) {   // eh 0: row g; 1: row g+8
                int m = m0 + warp_m * 64 + mt * 16 + g + eh * 8;
                int n = n0 + warp_n * 32 + j * 8 + cq;
                float v0 = acc[mt][j][eh * 2 + 0] + bias[n];
                float v1 = acc[mt][j][eh * 2 + 1] + bias[n + 1];
                if (MODE == 0) {
                    int which = n >> 11;
                    int h = (n >> 7) & 15;
                    int d = n & 127;
                    int b = m >> 11;
                    int t = m & 2047;
                    size_t idx = (((size_t)b * HH + h) * TT + t) * DD + d;
                    if (which == 0) { v0 *= QKSCALE; v1 *= QKSCALE; }
                    uint32_t hw, lw;
                    split2(v0, v1, hw, lw);
                    __nv_bfloat16 *ph, *pl;
                    if (which == 0)      { ph = g_qh; pl = g_ql; }
                    else if (which == 1) { ph = g_kh; pl = g_kl; }
                    else                 { ph = g_vh; pl = g_vl; }
                    *(uint32_t*)(ph + idx) = hw;
                    *(uint32_t*)(pl + idx) = lw;
                } else {
                    Cout[(size_t)m * Ntot + n]     = v0;
                    Cout[(size_t)m * Ntot + n + 1] = v1;
                }
            }
}

// ---------------------------------------------------------------------------
// HMMA flash attention (causal). 1 CTA = 64 q-rows of one (b,h); 4 warps,
// warp owns 16 q-rows. QK^T: 3-pass hi/lo; PV: 3-pass with P hi/lo register
// repack. V via ldmatrix.trans. Smem 96KB (Qh,Ql,Kh,Kl,Vh,Vl tiles 64x128).
// ---------------------------------------------------------------------------
#define ATTN_SMEM 98304
#define OQH 0
#define OQL 16384
#define OKH 32768
#define OKL 49152
#define OVH 65536
#define OVL 81920

__global__ __launch_bounds__(128) void attn_mma_kernel()
{
    extern __shared__ char smem[];
    const uint32_t sb = smem_u32(smem);

    const int tid = threadIdx.x;
    const int lane = tid & 31;
    const int w = tid >> 5;
    const int qt = (int)gridDim.x - 1 - (int)blockIdx.x;  // big tiles first
    const int h = blockIdx.y;
    const int b = blockIdx.z;

    const size_t base = (((size_t)b * HH + h) * TT) * DD;  // elem offset

    // --- load Q tiles (hi/lo) ---
    {
        const __nv_bfloat16* srcs[2] = {g_qh, g_ql};
        const uint32_t offs[2] = {OQH, OQL};
#pragma unroll
        for (int t = 0; t < 2; t++) {
            const __nv_bfloat16* gp = srcs[t] + base + (size_t)(qt * 64) * DD;
#pragma unroll
            for (int i = 0; i < 8; i++) {
                int chunk = i * 128 + tid;
                int row = chunk >> 4, c = chunk & 15;
                cp16(sb + offs[t] + row * 256 + ((c ^ (row & 7)) << 4),
                     gp + (size_t)row * DD + c * 8);
            }
        }
        CP_COMMIT();
    }

    const int g = lane >> 2, cq = (lane & 3) * 2;
    const uint32_t qrow = (uint32_t)(w * 16 + (lane & 15));

    float oacc[16][4];
#pragma unroll
    for (int nt = 0; nt < 16; nt++)
#pragma unroll
        for (int e = 0; e < 4; e++) oacc[nt][e] = 0.f;
    float mrow[2] = {-1e30f, -1e30f};
    float lrow[2] = {0.f, 0.f};

    for (int jt = 0; jt <= qt; jt++) {
        if (jt > 0) __syncthreads();   // smem reads of prev tile done
        // --- load K,V tiles (hi/lo) ---
        {
            const __nv_bfloat16* srcs[4] = {g_kh, g_kl, g_vh, g_vl};
            const uint32_t offs[4] = {OKH, OKL, OVH, OVL};
#pragma unroll
            for (int t = 0; t < 4; t++) {
                const __nv_bfloat16* gp = srcs[t] + base + (size_t)(jt * 64) * DD;
#pragma unroll
                for (int i = 0; i < 8; i++) {
                    int chunk = i * 128 + tid;
                    int row = chunk >> 4, c = chunk & 15;
                    cp16(sb + offs[t] + row * 256 + ((c ^ (row & 7)) << 4),
                         gp + (size_t)row * DD + c * 8);
                }
            }
            CP_COMMIT();
            CP_WAIT(0);
            __syncthreads();
        }

        // --- S = Q K^T (3-pass) ---
        float sacc[8][4];
#pragma unroll
        for (int j = 0; j < 8; j++)
#pragma unroll
            for (int e = 0; e < 4; e++) sacc[j][e] = 0.f;

#pragma unroll
        for (int kc = 0; kc < 8; kc++) {
            uint32_t aQh[4], aQl[4];
            {
                uint32_t c = (uint32_t)(kc * 2 + (lane >> 4));
                uint32_t so = qrow * 256 + ((c ^ (qrow & 7)) << 4);
                ldsm4(aQh[0], aQh[1], aQh[2], aQh[3], sb + OQH + so);
                ldsm4(aQl[0], aQl[1], aQl[2], aQl[3], sb + OQL + so);
            }
#pragma unroll
            for (int jg = 0; jg < 4; jg++) {
                uint32_t bKh[4], bKl[4];
                uint32_t r = (uint32_t)(jg * 16 + (lane & 7) + ((lane >> 4) & 1) * 8);
                uint32_t c = (uint32_t)(kc * 2 + ((lane >> 3) & 1));
                uint32_t so = r * 256 + ((c ^ (r & 7)) << 4);
                ldsm4(bKh[0], bKh[1], bKh[2], bKh[3], sb + OKH + so);
                ldsm4(bKl[0], bKl[1], bKl[2], bKl[3], sb + OKL + so);
#pragma unroll
                for (int jj = 0; jj < 2; jj++) {
                    const int j = jg * 2 + jj, hf = jj * 2;
                    mma16816(sacc[j], aQh, bKh[hf], bKh[hf + 1]);
                    mma16816(sacc[j], aQh, bKl[hf], bKl[hf + 1]);
                    mma16816(sacc[j], aQl, bKh[hf], bKh[hf + 1]);
                }
            }
        }

        // --- causal mask on diagonal tile ---
        if (jt == qt) {
#pragma unroll
            for (int j = 0; j < 8; j++)
#pragma unroll
                for (int e = 0; e < 4; e++) {
                    int col = j * 8 + cq + (e & 1);
                    int row = w * 16 + g + (e >> 1) * 8;
                    if (col > row) sacc[j][e] = -1e30f;
                }
        }

        // --- online softmax ---
        float nmax0 = -1e30f, nmax1 = -1e30f;
#pragma unroll
        for (int j = 0; j < 8; j++) {
            nmax0 = fmaxf(nmax0, fmaxf(sacc[j][0], sacc[j][1]));
            nmax1 = fmaxf(nmax1, fmaxf(sacc[j][2], sacc[j][3]));
        }
        nmax0 = fmaxf(nmax0, __shfl_xor_sync(0xffffffffu, nmax0, 1));
        nmax0 = fmaxf(nmax0, __shfl_xor_sync(0xffffffffu, nmax0, 2));
        nmax1 = fmaxf(nmax1, __shfl_xor_sync(0xffffffffu, nmax1, 1));
        nmax1 = fmaxf(nmax1, __shfl_xor_sync(0xffffffffu, nmax1, 2));
        float nm0 = fmaxf(mrow[0], nmax0), nm1 = fmaxf(mrow[1], nmax1);
        float alpha0 = __expf(mrow[0] - nm0), alpha1 = __expf(mrow[1] - nm1);
        mrow[0] = nm0; mrow[1] = nm1;

        float rsum0 = 0.f, rsum1 = 0.f;
#pragma unroll
        for (int j = 0; j < 8; j++) {
            float p0 = __expf(sacc[j][0] - nm0);
            float p1 = __expf(sacc[j][1] - nm0);
            float p2 = __expf(sacc[j][2] - nm1);
            float p3 = __expf(sacc[j][3] - nm1);
            sacc[j][0] = p0; sacc[j][1] = p1; sacc[j][2] = p2; sacc[j][3] = p3;
            rsum0 += p0 + p1;
            rsum1 += p2 + p3;
        }
        rsum0 += __shfl_xor_sync(0xffffffffu, rsum0, 1);
        rsum0 += __shfl_xor_sync(0xffffffffu, rsum0, 2);
        rsum1 += __shfl_xor_sync(0xffffffffu, rsum1, 1);
        rsum1 += __shfl_xor_sync(0xffffffffu, rsum1, 2);
        lrow[0] = lrow[0] * alpha0 + rsum0;
        lrow[1] = lrow[1] * alpha1 + rsum1;

#pragma unroll
        for (int nt = 0; nt < 16; nt++) {
            oacc[nt][0] *= alpha0; oacc[nt][1] *= alpha0;
            oacc[nt][2] *= alpha1; oacc[nt][3] *= alpha1;
        }

        // --- O += P V (3-pass, P repacked from S fragments) ---
#pragma unroll
        for (int kt = 0; kt < 4; kt++) {
            uint32_t aPh[4], aPl[4];
            split2(sacc[2 * kt][0],     sacc[2 * kt][1],     aPh[0], aPl[0]);
            split2(sacc[2 * kt][2],     sacc[2 * kt][3],     aPh[1], aPl[1]);
            split2(sacc[2 * kt + 1][0], sacc[2 * kt + 1][1], aPh[2], aPl[2]);
            split2(sacc[2 * kt + 1][2], sacc[2 * kt + 1][3], aPh[3], aPl[3]);
#pragma unroll
            for (int nt2 = 0; nt2 < 8; nt2++) {
                uint32_t bVh[4], bVl[4];
                uint32_t r = (uint32_t)(kt * 16 + (lane & 15));
                uint32_t c = (uint32_t)(nt2 * 2 + (lane >> 4));
                uint32_t so = r * 256 + ((c ^ (r & 7)) << 4);
                ldsm4t(bVh[0], bVh[1], bVh[2], bVh[3], sb + OVH + so);
                ldsm4t(bVl[0], bVl[1], bVl[2], bVl[3], sb + OVL + so);
                mma16816(oacc[nt2 * 2],     aPh, bVh[0], bVh[1]);
                mma16816(oacc[nt2 * 2],     aPh, bVl[0], bVl[1]);
                mma16816(oacc[nt2 * 2],     aPl, bVh[0], bVh[1]);
                mma16816(oacc[nt2 * 2 + 1], aPh, bVh[2], bVh[3]);
                mma16816(oacc[nt2 * 2 + 1], aPh, bVl[2], bVl[3]);
                mma16816(oacc[nt2 * 2 + 1], aPl, bVh[2], bVh[3]);
            }
        }
    }

    // --- epilogue: normalize, split hi/lo, write [B,T,C] ---
    const float inv0 = 1.f / lrow[0], inv1 = 1.f / lrow[1];
    const int q0 = qt * 64 + w * 16 + g;
#pragma unroll
    for (int nt = 0; nt < 16; nt++) {
        int d = nt * 8 + cq;
        {
            float v0 = oacc[nt][0] * inv0, v1 = oacc[nt][1] * inv0;
            uint32_t hw, lw;
            split2(v0, v1, hw, lw);
            size_t o = ((size_t)b * TT + q0) * CC + (size_t)h * DD + d;
            *(uint32_t*)(g_aoh + o) = hw;
            *(uint32_t*)(g_aol + o) = lw;
        }
        {
            float v0 = oacc[nt][2] * inv1, v1 = oacc[nt][3] * inv1;
            uint32_t hw, lw;
            split2(v0, v1, hw, lw);
            size_t o = ((size_t)b * TT + q0 + 8) * CC + (size_t)h * DD + d;
            *(uint32_t*)(g_aoh + o) = hw;
            *(uint32_t*)(g_aol + o) = lw;
        }
    }
}

// ---------------------------------------------------------------------------
extern "C" void kernel_launch(void* const* d_in, const int* in_sizes, int n_in,
                              void* d_out, int out_size)
{
    (void)in_sizes; (void)n_in; (void)out_size;
    const float* x     = (const float*)d_in[0];
    const float* Wqkv  = (const float*)d_in[1];
    const float* bqkv  = (const float*)d_in[2];
    const float* Wproj = (const float*)d_in[3];
    const float* bproj = (const float*)d_in[4];
    float* out = (float*)d_out;

    cudaFuncSetAttribute(attn_mma_kernel,
                         cudaFuncAttributeMaxDynamicSharedMemorySize, ATTN_SMEM);
    cudaFuncSetAttribute(hmma_gemm<0>,
                         cudaFuncAttributeMaxDynamicSharedMemorySize, GEMM_SMEM);
    cudaFuncSetAttribute(hmma_gemm<1>,
                         cudaFuncAttributeMaxDynamicSharedMemorySize, GEMM_SMEM);

    __nv_bfloat16 *xh, *xl, *wqh, *wql, *wph, *wpl, *aoh, *aol;
    cudaGetSymbolAddress((void**)&xh, g_xh);
    cudaGetSymbolAddress((void**)&xl, g_xl);
    cudaGetSymbolAddress((void**)&wqh, g_wqh);
    cudaGetSymbolAddress((void**)&wql, g_wql);
    cudaGetSymbolAddress((void**)&wph, g_wph);
    cudaGetSymbolAddress((void**)&wpl, g_wpl);
    cudaGetSymbolAddress((void**)&aoh, g_aoh);
    cudaGetSymbolAddress((void**)&aol, g_aol);

    // 1) Split to bf16 hi/lo (weights transposed to [N,K])
    convert_x_kernel<<<4096, 256>>>(x, xh, xl, (BB * TT * CC) / 4);
    convert_wT_kernel<<<dim3(3 * CC / 32, CC / 32), 256>>>(Wqkv, wqh, wql, CC, 3 * CC);
    convert_wT_kernel<<<dim3(CC / 32, CC / 32), 256>>>(Wproj, wph, wpl, CC, CC);

    // 2) QKV projection (HMMA), emits q/k/v bf16 hi/lo
    hmma_gemm<0><<<dim3(48, 64), 256, GEMM_SMEM>>>(
        xh, xl, wqh, wql, bqkv, nullptr, 3 * CC, CC);

    // 3) Causal flash attention on tensor cores
    attn_mma_kernel<<<dim3(TT / 64, HH, BB), 128, ATTN_SMEM>>>();

    // 4) Output projection (HMMA)
    hmma_gemm<1><<<dim3(16, 64), 256, GEMM_SMEM>>>(
        aoh, aol, wph, wpl, bproj, out, CC, CC);
}